// round 4
// baseline (speedup 1.0000x reference)
#include <cuda_runtime.h>

// ---------------------------------------------------------------------------
// TSDCD fused kernel, GB300 / sm_103a
//
// reference:
//   E[j,k] = exp(-mask_param[j,k]);  adj = u / (E + u*(1-E))   (== sigmoid(mp+logit(u)))
//   fixed mask: column k>=64 keeps all j except j==k; column k<64 keeps only j==k
//   s[b,k,j] = adj[b,j,k] * all_var[b,j];  all_var = cat(z, x)
//   h  = s @ W0[k] + b0[k]; leaky(0.01); @ W1[k] + b1[k]; leaky; . W2[k] + b2[k] -> mu[b,k]
//   logp = -0.5*((av-mu)/std)^2 - 0.5*logvar - 0.5*log(2pi);  recons = mean_b sum_k
// out: [0]=recons, [1 .. 1+B*D)=mu row-major, [1+B*D .. +D)=std
// ---------------------------------------------------------------------------

#define DTOT 320
#define DZ   64
#define DX   256
#define KOBS 256
#define BATCH 1024
#define NEG  0.01f
#define HLOG2PI 0.91893853320467274178f

// main-kernel shared layout (float offsets)
#define W0_STRIDE 5124          // 320*16 + 4  (mod 32 = 4 -> conflict-free, 16B aligned)
#define W1_STRIDE 260           // 256 + 4
#define AV_STRIDE 161           // 160 + 1
#define SM_W0 0
#define SM_W1 (SM_W0 + 8*W0_STRIDE)     // 40992
#define SM_AV (SM_W1 + 8*W1_STRIDE)     // 43072
#define SM_EA (SM_AV + 32*AV_STRIDE)    // 48224  (float2 region, 320*8 entries)
#define SM_B0 (SM_EA + 320*8*2)         // 53344
#define SM_B1 (SM_B0 + 128)             // 53472
#define SM_W2 (SM_B1 + 128)             // 53600
#define SM_B2 (SM_W2 + 128)             // 53728
#define SM_RED (SM_B2 + 8)              // 53736
#define SM_TOTAL (SM_RED + 256)         // 53992 floats = 215968 bytes
#define SMEM_BYTES (SM_TOTAL * 4)

__device__ float2 g_EA[DTOT * KOBS];    // (E, 1-E) for observed columns, [j][k-64]
__device__ float  g_partials[384];      // 0..127 main CTAs, 128..383 latent blocks

// ---- packed f32x2 helpers --------------------------------------------------
static __device__ __forceinline__ unsigned long long pack2(float lo, float hi) {
    unsigned long long r;
    asm("mov.b64 %0, {%1, %2};" : "=l"(r) : "f"(lo), "f"(hi));
    return r;
}
static __device__ __forceinline__ void unpack2(unsigned long long v, float& lo, float& hi) {
    asm("mov.b64 {%0, %1}, %2;" : "=f"(lo), "=f"(hi) : "l"(v));
}
static __device__ __forceinline__ unsigned long long ffma2(unsigned long long a,
                                                           unsigned long long b,
                                                           unsigned long long c) {
    unsigned long long d;
    asm("fma.rn.f32x2 %0, %1, %2, %3;" : "=l"(d) : "l"(a), "l"(b), "l"(c));
    return d;
}

// ---------------------------------------------------------------------------
// precompute: EA table + std output
// ---------------------------------------------------------------------------
__global__ void precompute_kernel(const float* __restrict__ mask_param,
                                  const float* __restrict__ logvar,
                                  float* __restrict__ out) {
    int idx = blockIdx.x * 256 + threadIdx.x;
    if (idx < DTOT * KOBS) {
        int j  = idx >> 8;
        int ko = idx & 255;
        float E = __expf(-__ldg(mask_param + (size_t)j * DTOT + DZ + ko));
        g_EA[idx] = make_float2(E, 1.0f - E);
    }
    if (idx < DTOT) {
        out[1 + BATCH * DTOT + idx] = expf(0.5f * __ldg(logvar + idx));
    }
}

// ---------------------------------------------------------------------------
// main kernel: observed k in [64,320)
// grid (32 kg, 4 bsplit) = 128 CTAs (1 wave), 256 threads, ~216KB dyn smem
// thread identity: k8 = tid&7 (8 k per CTA), blane = tid>>3 (32 b per pass)
// per-warp u load = 8 consecutive k x 4 b -> four full 32B sectors, 0 waste
// ---------------------------------------------------------------------------
__global__ void __launch_bounds__(256, 1)
main_kernel(const float* __restrict__ x, const float* __restrict__ z,
            const float* __restrict__ u,
            const float* __restrict__ W0, const float* __restrict__ b0,
            const float* __restrict__ W1, const float* __restrict__ b1,
            const float* __restrict__ W2, const float* __restrict__ b2,
            const float* __restrict__ logvar,
            float* __restrict__ out) {
    extern __shared__ float smem[];
    float*  W0s = smem + SM_W0;
    float*  W1s = smem + SM_W1;
    float*  avs = smem + SM_AV;
    float2* EAs = (float2*)(smem + SM_EA);
    float*  b0s = smem + SM_B0;
    float*  b1s = smem + SM_B1;
    float*  W2s = smem + SM_W2;
    float*  b2s = smem + SM_B2;
    float*  red = smem + SM_RED;

    const int tid    = threadIdx.x;
    const int kg     = blockIdx.x;           // 0..31
    const int bsplit = blockIdx.y;           // 0..3
    const int kbase  = DZ + kg * 8;
    const int k8     = tid & 7;
    const int blane  = tid >> 3;             // 0..31
    const int kglob  = kbase + k8;

    // ---- CTA-resident tables ----
    for (int i = tid; i < 8 * 1280; i += 256) {           // W0 slice, float4
        int kk = i / 1280, r = i % 1280;
        ((float4*)(W0s + kk * W0_STRIDE))[r] =
            ((const float4*)(W0 + (size_t)(kbase + kk) * 5120))[r];
    }
    for (int i = tid; i < 8 * 64; i += 256) {             // W1 slice, float4
        int kk = i / 64, r = i % 64;
        ((float4*)(W1s + kk * W1_STRIDE))[r] =
            ((const float4*)(W1 + (size_t)(kbase + kk) * 256))[r];
    }
    for (int i = tid; i < 320 * 8; i += 256) {            // EA slice
        int j = i >> 3, kk = i & 7;
        EAs[i] = g_EA[(size_t)j * KOBS + kg * 8 + kk];
    }
    if (tid < 128) {
        b0s[tid] = b0[kbase * 16 + tid];
        b1s[tid] = b1[kbase * 16 + tid];
        W2s[tid] = W2[kbase * 16 + tid];
    }
    if (tid < 8) b2s[tid] = b2[kbase + tid];
    __syncthreads();

    const float lv   = __ldg(logvar + kglob);
    const float istd = __expf(-0.5f * lv);
    const float lpc  = -0.5f * lv - HLOG2PI;
    float lpsum = 0.0f;

    const float* avrow = avs + blane * AV_STRIDE;
    const float* W0k   = W0s + k8 * W0_STRIDE;

#pragma unroll 1
    for (int pass = 0; pass < 8; pass++) {
        const int bbase = bsplit * 256 + pass * 32;
        const int b     = bbase + blane;
        const float* up = u + (size_t)b * (DTOT * DTOT) + kglob;

        unsigned long long acc[8];
#pragma unroll
        for (int q = 0; q < 8; q++)
            acc[q] = pack2(b0s[k8 * 16 + 2 * q], b0s[k8 * 16 + 2 * q + 1]);

#pragma unroll 1
        for (int chunk = 0; chunk < 2; chunk++) {
            const int cb = chunk * 160;
            __syncthreads();                 // previous chunk consumers done
            for (int idx = tid; idx < 32 * 160; idx += 256) {
                int bb = idx / 160, jl = idx - bb * 160;
                int jg = cb + jl;
                int bg = bbase + bb;
                float v = (jg < DZ) ? __ldg(z + (size_t)bg * DZ + jg)
                                    : __ldg(x + (size_t)bg * DX + (jg - DZ));
                avs[bb * AV_STRIDE + jl] = v;
            }
            __syncthreads();                 // av tile ready

            float ucur[8];
#pragma unroll
            for (int t = 0; t < 8; t++)
                ucur[t] = __ldg(up + (size_t)(cb + t) * DTOT);

#pragma unroll 1
            for (int jj = 0; jj < 160; jj += 8) {
                float unext[8];
#pragma unroll
                for (int t = 0; t < 8; t++) {
                    int jn = cb + jj + 8 + t;
                    if (jn >= DTOT) jn = 0;          // clamped dummy prefetch
                    unext[t] = __ldg(up + (size_t)jn * DTOT);
                }
#pragma unroll
                for (int t = 0; t < 8; t++) {
                    const int jl = jj + t;
                    const int jg = cb + jl;
                    float uu = ucur[t];
                    float av = avrow[jl];
                    float2 ea = EAs[jg * 8 + k8];
                    float den = fmaf(uu, ea.y, ea.x);       // E + u*(1-E)
                    float s = __fdividef(uu * av, den);
                    unsigned long long ss = pack2(s, s);
                    const ulonglong2* wr = (const ulonglong2*)(W0k + jg * 16);
#pragma unroll
                    for (int q = 0; q < 4; q++) {
                        ulonglong2 w = wr[q];
                        acc[2 * q]     = ffma2(ss, w.x, acc[2 * q]);
                        acc[2 * q + 1] = ffma2(ss, w.y, acc[2 * q + 1]);
                    }
                }
#pragma unroll
                for (int t = 0; t < 8; t++) ucur[t] = unext[t];
            }
        }

        // ---- diagonal correction (j == kglob was wrongly included above) ----
        float u_kk  = __ldg(u + (size_t)b * (DTOT * DTOT) + (size_t)kglob * DTOT + kglob);
        float av_kk = __ldg(x + (size_t)b * DX + (kglob - DZ));
        float2 eak  = EAs[kglob * 8 + k8];
        float skk   = __fdividef(u_kk * av_kk, fmaf(u_kk, eak.y, eak.x));
        const float* w0kk = W0k + kglob * 16;

        float hv[16];
#pragma unroll
        for (int q = 0; q < 8; q++) {
            float lo, hi;
            unpack2(acc[q], lo, hi);
            float c0 = fmaf(-skk, w0kk[2 * q],     lo);
            float c1 = fmaf(-skk, w0kk[2 * q + 1], hi);
            hv[2 * q]     = fmaxf(c0, NEG * c0);
            hv[2 * q + 1] = fmaxf(c1, NEG * c1);
        }

        // ---- layer 1 ----
        float gv[16];
#pragma unroll
        for (int gg = 0; gg < 16; gg++) gv[gg] = b1s[k8 * 16 + gg];
#pragma unroll
        for (int hh = 0; hh < 16; hh++) {
            float hvv = hv[hh];
            const float4* w1r = (const float4*)(W1s + k8 * W1_STRIDE + hh * 16);
#pragma unroll
            for (int q = 0; q < 4; q++) {
                float4 w = w1r[q];
                gv[4 * q + 0] = fmaf(hvv, w.x, gv[4 * q + 0]);
                gv[4 * q + 1] = fmaf(hvv, w.y, gv[4 * q + 1]);
                gv[4 * q + 2] = fmaf(hvv, w.z, gv[4 * q + 2]);
                gv[4 * q + 3] = fmaf(hvv, w.w, gv[4 * q + 3]);
            }
        }

        // ---- layer 2 ----
        float mu = b2s[k8];
#pragma unroll
        for (int gg = 0; gg < 16; gg++) {
            float gl = fmaxf(gv[gg], NEG * gv[gg]);
            mu = fmaf(gl, W2s[k8 * 16 + gg], mu);
        }
        out[1 + (size_t)b * DTOT + kglob] = mu;

        float d = (av_kk - mu) * istd;
        lpsum += fmaf(-0.5f * d, d, lpc);
    }

    // ---- deterministic CTA reduction ----
    red[tid] = lpsum;
    __syncthreads();
    for (int sft = 128; sft > 0; sft >>= 1) {
        if (tid < sft) red[tid] += red[tid + sft];
        __syncthreads();
    }
    if (tid == 0) g_partials[bsplit * 32 + kg] = red[0];
}

// ---------------------------------------------------------------------------
// latent kernel: k in [0,64) -> only j==k contributes
// grid (64 k, 4 bq), 256 threads, 1 batch per thread
// ---------------------------------------------------------------------------
__global__ void __launch_bounds__(256)
latent_kernel(const float* __restrict__ z, const float* __restrict__ u,
              const float* __restrict__ mask_param,
              const float* __restrict__ W0, const float* __restrict__ b0,
              const float* __restrict__ W1, const float* __restrict__ b1,
              const float* __restrict__ W2, const float* __restrict__ b2,
              const float* __restrict__ logvar,
              float* __restrict__ out) {
    __shared__ float W1s[256], W0r[16], b0r[16], b1r[16], W2r[16];
    __shared__ float red[256];

    const int tid = threadIdx.x;
    const int k   = blockIdx.x;
    const int bq  = blockIdx.y;
    const int b   = bq * 256 + tid;

    if (tid < 16) {
        W0r[tid] = __ldg(W0 + ((size_t)k * DTOT + k) * 16 + tid);
        b0r[tid] = __ldg(b0 + k * 16 + tid);
        b1r[tid] = __ldg(b1 + k * 16 + tid);
        W2r[tid] = __ldg(W2 + k * 16 + tid);
    }
    W1s[tid] = __ldg(W1 + (size_t)k * 256 + tid);
    __syncthreads();

    float E  = __expf(-__ldg(mask_param + (size_t)k * DTOT + k));
    float uu = __ldg(u + (size_t)b * (DTOT * DTOT) + (size_t)k * DTOT + k);
    float zv = __ldg(z + (size_t)b * DZ + k);
    float adj = __fdividef(uu, fmaf(uu, 1.0f - E, E));
    float val = adj * zv;

    float hv[16];
#pragma unroll
    for (int i = 0; i < 16; i++) {
        float c = fmaf(val, W0r[i], b0r[i]);
        hv[i] = fmaxf(c, NEG * c);
    }
    float gv[16];
#pragma unroll
    for (int gg = 0; gg < 16; gg++) gv[gg] = b1r[gg];
#pragma unroll
    for (int hh = 0; hh < 16; hh++) {
        float hvv = hv[hh];
#pragma unroll
        for (int gg = 0; gg < 16; gg++)
            gv[gg] = fmaf(hvv, W1s[hh * 16 + gg], gv[gg]);
    }
    float mu = __ldg(b2 + k);
#pragma unroll
    for (int gg = 0; gg < 16; gg++) {
        float gl = fmaxf(gv[gg], NEG * gv[gg]);
        mu = fmaf(gl, W2r[gg], mu);
    }
    out[1 + (size_t)b * DTOT + k] = mu;

    float lv = __ldg(logvar + k);
    float istd = __expf(-0.5f * lv);
    float d = (zv - mu) * istd;
    red[tid] = fmaf(-0.5f * d, d, -0.5f * lv - HLOG2PI);
    __syncthreads();
    for (int sft = 128; sft > 0; sft >>= 1) {
        if (tid < sft) red[tid] += red[tid + sft];
        __syncthreads();
    }
    if (tid == 0) g_partials[128 + k * 4 + bq] = red[0];
}

// ---------------------------------------------------------------------------
__global__ void final_kernel(float* __restrict__ out) {
    if (threadIdx.x == 0) {
        float s = 0.0f;
        for (int i = 0; i < 384; i++) s += g_partials[i];
        out[0] = s * (1.0f / 1024.0f);
    }
}

// ---------------------------------------------------------------------------
extern "C" void kernel_launch(void* const* d_in, const int* in_sizes, int n_in,
                              void* d_out, int out_size) {
    const float* x      = (const float*)d_in[0];
    const float* z      = (const float*)d_in[1];
    const float* u      = (const float*)d_in[2];
    const float* mp     = (const float*)d_in[3];
    const float* W0     = (const float*)d_in[4];
    const float* b0     = (const float*)d_in[5];
    const float* W1     = (const float*)d_in[6];
    const float* b1     = (const float*)d_in[7];
    const float* W2     = (const float*)d_in[8];
    const float* b2     = (const float*)d_in[9];
    const float* logvar = (const float*)d_in[10];
    float* out = (float*)d_out;

    cudaFuncSetAttribute(main_kernel, cudaFuncAttributeMaxDynamicSharedMemorySize,
                         SMEM_BYTES);

    precompute_kernel<<<320, 256>>>(mp, logvar, out);
    main_kernel<<<dim3(32, 4), 256, SMEM_BYTES>>>(x, z, u, W0, b0, W1, b1, W2, b2,
                                                  logvar, out);
    latent_kernel<<<dim3(64, 4), 256>>>(z, u, mp, W0, b0, W1, b1, W2, b2, logvar, out);
    final_kernel<<<1, 32>>>(out);
}

// round 9
// speedup vs baseline: 1.3090x; 1.3090x over previous
#include <cuda_runtime.h>

// ---------------------------------------------------------------------------
// TSDCD fused kernel, GB300 / sm_103a  — BF=4 batch-blocked main kernel
//
//   E[j,k] = exp(-mask_param[j,k]);  adj = u / (E + u*(1-E))  (== sigmoid(mp+logit(u)))
//   fixed mask: column k>=64 keeps all j except j==k; column k<64 keeps only j==k
//   s[b,k,j] = adj[b,j,k] * all_var[b,j];  all_var = cat(z, x)
//   h = s@W0[k]+b0; leaky(.01); @W1[k]+b1; leaky; .W2[k]+b2 -> mu[b,k]
//   logp = -0.5*((av-mu)/std)^2 - 0.5*logvar - 0.5*log(2pi); recons = mean_b sum_k
// out: [0]=recons, [1..1+B*D)=mu row-major, [1+B*D..+D)=std
// ---------------------------------------------------------------------------

#define DTOT 320
#define DZ   64
#define DX   256
#define BATCH 1024
#define NEG  0.01f
#define HLOG2PI 0.91893853320467274178f
#define BF 4

// shared layout (float offsets)
#define W0_STRIDE 5124          // 320*16+4 : mod32=4 -> conflict-free, 16B aligned
#define W1_STRIDE 260
#define AV_STRIDE 68            // 64+4 : mod32=4, float4-aligned
#define SM_W0 0                                  // 40992
#define SM_W1 (SM_W0 + 8*W0_STRIDE)              // 2080
#define SM_AV (SM_W1 + 8*W1_STRIDE)              // 128*68 = 8704
#define SM_EA (SM_AV + 128*AV_STRIDE)            // 2560 float2 = 5120
#define SM_B0 (SM_EA + 5120)
#define SM_B1 (SM_B0 + 128)
#define SM_W2 (SM_B1 + 128)
#define SM_B2 (SM_W2 + 128)
#define SM_RED (SM_B2 + 8)
#define SM_TOTAL (SM_RED + 256)                  // 57544 floats = 230176 B
#define SMEM_BYTES (SM_TOTAL * 4)

__device__ float g_partials[384];   // 0..127 main CTAs, 128..383 latent blocks

typedef unsigned long long ull;

static __device__ __forceinline__ ull pack2(float lo, float hi) {
    ull r; asm("mov.b64 %0, {%1, %2};" : "=l"(r) : "f"(lo), "f"(hi)); return r;
}
static __device__ __forceinline__ void unpack2(ull v, float& lo, float& hi) {
    asm("mov.b64 {%0, %1}, %2;" : "=f"(lo), "=f"(hi) : "l"(v));
}
static __device__ __forceinline__ ull ffma2(ull a, ull b, ull c) {
    ull d; asm("fma.rn.f32x2 %0, %1, %2, %3;" : "=l"(d) : "l"(a), "l"(b), "l"(c));
    return d;
}

// ---------------------------------------------------------------------------
// main kernel: observed k in [64,320)
// grid (32 kg, 4 bsplit) = 128 CTAs, 256 threads, ~230KB dyn smem
// lanes: k8 = tid&7 (8 k/CTA), blane = tid>>3 (32 b-lanes); BF=4 batches/thread
// per-warp u LDG = 8 consecutive k x 4 consecutive b -> 4 full 32B sectors
// ---------------------------------------------------------------------------
__global__ void __launch_bounds__(256, 1)
main_kernel(const float* __restrict__ x, const float* __restrict__ z,
            const float* __restrict__ u, const float* __restrict__ mp,
            const float* __restrict__ W0, const float* __restrict__ b0,
            const float* __restrict__ W1, const float* __restrict__ b1,
            const float* __restrict__ W2, const float* __restrict__ b2,
            const float* __restrict__ logvar,
            float* __restrict__ out) {
    extern __shared__ float smem[];
    float*  W0s = smem + SM_W0;
    float*  W1s = smem + SM_W1;
    float*  avs = smem + SM_AV;
    float2* EAs = (float2*)(smem + SM_EA);
    float*  b0s = smem + SM_B0;
    float*  b1s = smem + SM_B1;
    float*  W2s = smem + SM_W2;
    float*  b2s = smem + SM_B2;
    float*  red = smem + SM_RED;

    const int tid    = threadIdx.x;
    const int kg     = blockIdx.x;
    const int bsplit = blockIdx.y;
    const int kbase  = DZ + kg * 8;
    const int k8     = tid & 7;
    const int blane  = tid >> 3;
    const int kglob  = kbase + k8;

    // ---- CTA-resident tables ----
    for (int i = tid; i < 8 * 1280; i += 256) {           // W0 slice, float4
        int kk = i / 1280, r = i % 1280;
        ((float4*)(W0s + kk * W0_STRIDE))[r] =
            ((const float4*)(W0 + (size_t)(kbase + kk) * 5120))[r];
    }
    for (int i = tid; i < 8 * 64; i += 256) {             // W1 slice, float4
        int kk = i / 64, r = i % 64;
        ((float4*)(W1s + kk * W1_STRIDE))[r] =
            ((const float4*)(W1 + (size_t)(kbase + kk) * 256))[r];
    }
    for (int i = tid; i < 2560; i += 256) {               // EA from mask_param
        int j = i >> 3, kk = i & 7;
        float E = __expf(-__ldg(mp + (size_t)j * DTOT + kbase + kk));
        EAs[i] = make_float2(E, 1.0f - E);
    }
    if (tid < 128) {
        b0s[tid] = b0[kbase * 16 + tid];
        b1s[tid] = b1[kbase * 16 + tid];
        W2s[tid] = W2[kbase * 16 + tid];
    }
    if (tid < 8) b2s[tid] = b2[kbase + tid];
    __syncthreads();

    const float lv   = __ldg(logvar + kglob);
    const float istd = __expf(-0.5f * lv);
    const float lpc  = -0.5f * lv - HLOG2PI;
    float lpsum = 0.0f;

    const float* W0k = W0s + k8 * W0_STRIDE;

#pragma unroll 1
    for (int pass = 0; pass < 2; pass++) {
        const int bbase = bsplit * 256 + pass * 128;
        const float* up[BF];
#pragma unroll
        for (int o = 0; o < BF; o++)
            up[o] = u + (size_t)(bbase + blane + 32 * o) * (DTOT * DTOT) + kglob;

        ull acc[BF][8];
#pragma unroll
        for (int o = 0; o < BF; o++)
#pragma unroll
            for (int q = 0; q < 8; q++)
                acc[o][q] = pack2(b0s[k8 * 16 + 2 * q], b0s[k8 * 16 + 2 * q + 1]);

        float uc[4][BF];
#pragma unroll
        for (int t = 0; t < 4; t++)
#pragma unroll
            for (int o = 0; o < BF; o++)
                uc[t][o] = __ldg(up[o] + (size_t)t * DTOT);

#pragma unroll 1
        for (int chunk = 0; chunk < 5; chunk++) {
            const int cb = chunk * 64;
            __syncthreads();                 // previous chunk consumers done
            // fill av tile [128 b][64 j] as float4
            for (int q = tid; q < 128 * 16; q += 256) {
                int r = q >> 4, c4 = (q & 15) * 4;
                int jg = cb + c4;
                const float* src = (jg < DZ)
                    ? (z + (size_t)(bbase + r) * DZ + jg)
                    : (x + (size_t)(bbase + r) * DX + (jg - DZ));
                *(float4*)(avs + r * AV_STRIDE + c4) = *(const float4*)src;
            }
            __syncthreads();                 // av tile ready

#pragma unroll 1
            for (int jj = 0; jj < 64; jj += 4) {
                float un[4][BF];
#pragma unroll
                for (int t = 0; t < 4; t++) {
                    int jn = cb + jj + 4 + t;
                    if (jn > 319) jn = 319;          // tail dummy (in-bounds)
#pragma unroll
                    for (int o = 0; o < BF; o++)
                        un[t][o] = __ldg(up[o] + (size_t)jn * DTOT);
                }
                float4 av4[BF];
#pragma unroll
                for (int o = 0; o < BF; o++)
                    av4[o] = *(const float4*)(avs + (blane + 32 * o) * AV_STRIDE + jj);

#pragma unroll
                for (int t = 0; t < 4; t++) {
                    const int jg = cb + jj + t;
                    const float2 ea = EAs[jg * 8 + k8];
                    const ulonglong2* wrp = (const ulonglong2*)(W0k + jg * 16);
                    ulonglong2 wA = wrp[0], wB = wrp[1], wC = wrp[2], wD = wrp[3];
#pragma unroll
                    for (int o = 0; o < BF; o++) {
                        float uu = uc[t][o];
                        float av = (t == 0) ? av4[o].x : (t == 1) ? av4[o].y
                                 : (t == 2) ? av4[o].z : av4[o].w;
                        float den = fmaf(uu, ea.y, ea.x);       // E + u*(1-E)
                        float s   = __fdividef(uu * av, den);
                        ull ss = pack2(s, s);
                        acc[o][0] = ffma2(ss, wA.x, acc[o][0]);
                        acc[o][1] = ffma2(ss, wA.y, acc[o][1]);
                        acc[o][2] = ffma2(ss, wB.x, acc[o][2]);
                        acc[o][3] = ffma2(ss, wB.y, acc[o][3]);
                        acc[o][4] = ffma2(ss, wC.x, acc[o][4]);
                        acc[o][5] = ffma2(ss, wC.y, acc[o][5]);
                        acc[o][6] = ffma2(ss, wD.x, acc[o][6]);
                        acc[o][7] = ffma2(ss, wD.y, acc[o][7]);
                    }
                }
#pragma unroll
                for (int t = 0; t < 4; t++)
#pragma unroll
                    for (int o = 0; o < BF; o++) uc[t][o] = un[t][o];
            }
        }

        // ---- epilogue per batch: diag correction, layers 1/2, logp ----
#pragma unroll 1
        for (int o = 0; o < BF; o++) {
            const int b = bbase + blane + 32 * o;
            float u_kk  = __ldg(u + (size_t)b * (DTOT * DTOT) + (size_t)kglob * DTOT + kglob);
            float av_kk = __ldg(x + (size_t)b * DX + (kglob - DZ));
            float2 eak  = EAs[kglob * 8 + k8];
            float skk   = __fdividef(u_kk * av_kk, fmaf(u_kk, eak.y, eak.x));
            const float* w0kk = W0k + kglob * 16;

            float hv[16];
#pragma unroll
            for (int q = 0; q < 8; q++) {
                float lo, hi;
                unpack2(acc[o][q], lo, hi);
                float c0 = fmaf(-skk, w0kk[2 * q],     lo);
                float c1 = fmaf(-skk, w0kk[2 * q + 1], hi);
                hv[2 * q]     = fmaxf(c0, NEG * c0);
                hv[2 * q + 1] = fmaxf(c1, NEG * c1);
            }
            float gv[16];
#pragma unroll
            for (int gg = 0; gg < 16; gg++) gv[gg] = b1s[k8 * 16 + gg];
#pragma unroll
            for (int hh = 0; hh < 16; hh++) {
                float hvv = hv[hh];
                const float4* w1r = (const float4*)(W1s + k8 * W1_STRIDE + hh * 16);
#pragma unroll
                for (int q = 0; q < 4; q++) {
                    float4 w = w1r[q];
                    gv[4 * q + 0] = fmaf(hvv, w.x, gv[4 * q + 0]);
                    gv[4 * q + 1] = fmaf(hvv, w.y, gv[4 * q + 1]);
                    gv[4 * q + 2] = fmaf(hvv, w.z, gv[4 * q + 2]);
                    gv[4 * q + 3] = fmaf(hvv, w.w, gv[4 * q + 3]);
                }
            }
            float mu = b2s[k8];
#pragma unroll
            for (int gg = 0; gg < 16; gg++) {
                float gl = fmaxf(gv[gg], NEG * gv[gg]);
                mu = fmaf(gl, W2s[k8 * 16 + gg], mu);
            }
            out[1 + (size_t)b * DTOT + kglob] = mu;

            float d = (av_kk - mu) * istd;
            lpsum += fmaf(-0.5f * d, d, lpc);
        }
    }

    // ---- deterministic CTA reduction ----
    red[tid] = lpsum;
    __syncthreads();
    for (int sft = 128; sft > 0; sft >>= 1) {
        if (tid < sft) red[tid] += red[tid + sft];
        __syncthreads();
    }
    if (tid == 0) g_partials[bsplit * 32 + kg] = red[0];
}

// ---------------------------------------------------------------------------
// latent kernel: k in [0,64) -> only j==k contributes
// ---------------------------------------------------------------------------
__global__ void __launch_bounds__(256)
latent_kernel(const float* __restrict__ z, const float* __restrict__ u,
              const float* __restrict__ mp,
              const float* __restrict__ W0, const float* __restrict__ b0,
              const float* __restrict__ W1, const float* __restrict__ b1,
              const float* __restrict__ W2, const float* __restrict__ b2,
              const float* __restrict__ logvar,
              float* __restrict__ out) {
    __shared__ float W1s[256], W0r[16], b0r[16], b1r[16], W2r[16];
    __shared__ float red[256];

    const int tid = threadIdx.x;
    const int k   = blockIdx.x;
    const int bq  = blockIdx.y;
    const int b   = bq * 256 + tid;

    if (tid < 16) {
        W0r[tid] = __ldg(W0 + ((size_t)k * DTOT + k) * 16 + tid);
        b0r[tid] = __ldg(b0 + k * 16 + tid);
        b1r[tid] = __ldg(b1 + k * 16 + tid);
        W2r[tid] = __ldg(W2 + k * 16 + tid);
    }
    W1s[tid] = __ldg(W1 + (size_t)k * 256 + tid);
    __syncthreads();

    float E  = __expf(-__ldg(mp + (size_t)k * DTOT + k));
    float uu = __ldg(u + (size_t)b * (DTOT * DTOT) + (size_t)k * DTOT + k);
    float zv = __ldg(z + (size_t)b * DZ + k);
    float adj = __fdividef(uu, fmaf(uu, 1.0f - E, E));
    float val = adj * zv;

    float hv[16];
#pragma unroll
    for (int i = 0; i < 16; i++) {
        float c = fmaf(val, W0r[i], b0r[i]);
        hv[i] = fmaxf(c, NEG * c);
    }
    float gv[16];
#pragma unroll
    for (int gg = 0; gg < 16; gg++) gv[gg] = b1r[gg];
#pragma unroll
    for (int hh = 0; hh < 16; hh++) {
        float hvv = hv[hh];
#pragma unroll
        for (int gg = 0; gg < 16; gg++)
            gv[gg] = fmaf(hvv, W1s[hh * 16 + gg], gv[gg]);
    }
    float mu = __ldg(b2 + k);
#pragma unroll
    for (int gg = 0; gg < 16; gg++) {
        float gl = fmaxf(gv[gg], NEG * gv[gg]);
        mu = fmaf(gl, W2r[gg], mu);
    }
    out[1 + (size_t)b * DTOT + k] = mu;

    float lv = __ldg(logvar + k);
    float istd = __expf(-0.5f * lv);
    float d = (zv - mu) * istd;
    red[tid] = fmaf(-0.5f * d, d, -0.5f * lv - HLOG2PI);
    __syncthreads();
    for (int sft = 128; sft > 0; sft >>= 1) {
        if (tid < sft) red[tid] += red[tid + sft];
        __syncthreads();
    }
    if (tid == 0) g_partials[128 + k * 4 + bq] = red[0];
}

// ---------------------------------------------------------------------------
// final: 384-thread deterministic reduction + std output
// ---------------------------------------------------------------------------
__global__ void final_kernel(const float* __restrict__ logvar,
                             float* __restrict__ out) {
    __shared__ float red[384];
    const int tid = threadIdx.x;
    red[tid] = g_partials[tid];
    __syncthreads();
    if (tid < 128) red[tid] += red[tid + 256];
    __syncthreads();
    for (int sft = 128; sft > 0; sft >>= 1) {
        if (tid < sft) red[tid] += red[tid + sft];
        __syncthreads();
    }
    if (tid == 0) out[0] = red[0] * (1.0f / 1024.0f);
    if (tid < DTOT) out[1 + BATCH * DTOT + tid] = expf(0.5f * __ldg(logvar + tid));
}

// ---------------------------------------------------------------------------
extern "C" void kernel_launch(void* const* d_in, const int* in_sizes, int n_in,
                              void* d_out, int out_size) {
    const float* x      = (const float*)d_in[0];
    const float* z      = (const float*)d_in[1];
    const float* u      = (const float*)d_in[2];
    const float* mp     = (const float*)d_in[3];
    const float* W0     = (const float*)d_in[4];
    const float* b0     = (const float*)d_in[5];
    const float* W1     = (const float*)d_in[6];
    const float* b1     = (const float*)d_in[7];
    const float* W2     = (const float*)d_in[8];
    const float* b2     = (const float*)d_in[9];
    const float* logvar = (const float*)d_in[10];
    float* out = (float*)d_out;

    cudaFuncSetAttribute(main_kernel, cudaFuncAttributeMaxDynamicSharedMemorySize,
                         SMEM_BYTES);

    main_kernel<<<dim3(32, 4), 256, SMEM_BYTES>>>(x, z, u, mp, W0, b0, W1, b1,
                                                  W2, b2, logvar, out);
    latent_kernel<<<dim3(64, 4), 256>>>(z, u, mp, W0, b0, W1, b1, W2, b2, logvar, out);
    final_kernel<<<1, 384>>>(logvar, out);
}

// round 10
// speedup vs baseline: 1.3563x; 1.0361x over previous
#include <cuda_runtime.h>

// ---------------------------------------------------------------------------
// TSDCD fused kernel, GB300 / sm_103a — 512-thread / BF=2 main kernel (occ 2x)
//
//   E[j,k] = exp(-mask_param[j,k]);  adj = u / (E + u*(1-E))  (== sigmoid(mp+logit(u)))
//   fixed mask: column k>=64 keeps all j except j==k; column k<64 keeps only j==k
//   s[b,k,j] = adj[b,j,k] * all_var[b,j];  all_var = cat(z, x)
//   h = s@W0[k]+b0; leaky(.01); @W1[k]+b1; leaky; .W2[k]+b2 -> mu[b,k]
//   logp = -0.5*((av-mu)/std)^2 - 0.5*logvar - 0.5*log(2pi); recons = mean_b sum_k
// out: [0]=recons, [1..1+B*D)=mu row-major, [1+B*D..+D)=std
// ---------------------------------------------------------------------------

#define DTOT 320
#define DZ   64
#define DX   256
#define BATCH 1024
#define NEG  0.01f
#define HLOG2PI 0.91893853320467274178f
#define BF 2
#define NTHR 512

// shared layout (float offsets)
#define W0_STRIDE 5124          // 320*16+4 : mod32=4 -> conflict-free, 16B aligned
#define W1_STRIDE 260
#define AV_STRIDE 68            // 64+4 : mod32=4, float4-aligned
#define SM_W0 0                                  // 40992
#define SM_W1 (SM_W0 + 8*W0_STRIDE)              // 2080
#define SM_AV (SM_W1 + 8*W1_STRIDE)              // 128*68 = 8704
#define SM_EA (SM_AV + 128*AV_STRIDE)            // 2560 float2 = 5120
#define SM_B0 (SM_EA + 5120)
#define SM_B1 (SM_B0 + 128)
#define SM_W2 (SM_B1 + 128)
#define SM_B2 (SM_W2 + 128)
#define SM_RED (SM_B2 + 8)
#define SM_TOTAL (SM_RED + 512)                  // 57800 floats = 231200 B
#define SMEM_BYTES (SM_TOTAL * 4)

__device__ float g_partials[384];   // 0..127 main CTAs, 128..383 latent blocks

typedef unsigned long long ull;

static __device__ __forceinline__ ull pack2(float lo, float hi) {
    ull r; asm("mov.b64 %0, {%1, %2};" : "=l"(r) : "f"(lo), "f"(hi)); return r;
}
static __device__ __forceinline__ void unpack2(ull v, float& lo, float& hi) {
    asm("mov.b64 {%0, %1}, %2;" : "=f"(lo), "=f"(hi) : "l"(v));
}
static __device__ __forceinline__ ull ffma2(ull a, ull b, ull c) {
    ull d; asm("fma.rn.f32x2 %0, %1, %2, %3;" : "=l"(d) : "l"(a), "l"(b), "l"(c));
    return d;
}

// ---------------------------------------------------------------------------
// main kernel: observed k in [64,320)
// grid (32 kg, 4 bsplit) = 128 CTAs, 512 threads (16 warps/SM, occ 25%)
// lanes: k8 = tid&7 (8 k/CTA), blane = tid>>3 (64 b-lanes); BF=2 batches/thread
// per-warp u LDG = 8 consecutive k x 4 consecutive b -> 4 full 32B sectors
// ---------------------------------------------------------------------------
__global__ void __launch_bounds__(NTHR, 1)
main_kernel(const float* __restrict__ x, const float* __restrict__ z,
            const float* __restrict__ u, const float* __restrict__ mp,
            const float* __restrict__ W0, const float* __restrict__ b0,
            const float* __restrict__ W1, const float* __restrict__ b1,
            const float* __restrict__ W2, const float* __restrict__ b2,
            const float* __restrict__ logvar,
            float* __restrict__ out) {
    extern __shared__ float smem[];
    float*  W0s = smem + SM_W0;
    float*  W1s = smem + SM_W1;
    float*  avs = smem + SM_AV;
    float2* EAs = (float2*)(smem + SM_EA);
    float*  b0s = smem + SM_B0;
    float*  b1s = smem + SM_B1;
    float*  W2s = smem + SM_W2;
    float*  b2s = smem + SM_B2;
    float*  red = smem + SM_RED;

    const int tid    = threadIdx.x;
    const int kg     = blockIdx.x;
    const int bsplit = blockIdx.y;
    const int kbase  = DZ + kg * 8;
    const int k8     = tid & 7;
    const int blane  = tid >> 3;             // 0..63
    const int kglob  = kbase + k8;

    // ---- CTA-resident tables ----
    for (int i = tid; i < 8 * 1280; i += NTHR) {          // W0 slice, float4
        int kk = i / 1280, r = i % 1280;
        ((float4*)(W0s + kk * W0_STRIDE))[r] =
            ((const float4*)(W0 + (size_t)(kbase + kk) * 5120))[r];
    }
    for (int i = tid; i < 8 * 64; i += NTHR) {            // W1 slice, float4
        int kk = i / 64, r = i % 64;
        ((float4*)(W1s + kk * W1_STRIDE))[r] =
            ((const float4*)(W1 + (size_t)(kbase + kk) * 256))[r];
    }
    for (int i = tid; i < 2560; i += NTHR) {              // EA from mask_param
        int j = i >> 3, kk = i & 7;
        float E = __expf(-__ldg(mp + (size_t)j * DTOT + kbase + kk));
        EAs[i] = make_float2(E, 1.0f - E);
    }
    if (tid < 128) {
        b0s[tid] = b0[kbase * 16 + tid];
        b1s[tid] = b1[kbase * 16 + tid];
        W2s[tid] = W2[kbase * 16 + tid];
    }
    if (tid < 8) b2s[tid] = b2[kbase + tid];
    __syncthreads();

    const float lv   = __ldg(logvar + kglob);
    const float istd = __expf(-0.5f * lv);
    const float lpc  = -0.5f * lv - HLOG2PI;
    float lpsum = 0.0f;

    const float* W0k = W0s + k8 * W0_STRIDE;

#pragma unroll 1
    for (int pass = 0; pass < 2; pass++) {
        const int bbase = bsplit * 256 + pass * 128;
        const float* up[BF];
#pragma unroll
        for (int o = 0; o < BF; o++)
            up[o] = u + (size_t)(bbase + blane + 64 * o) * (DTOT * DTOT) + kglob;

        ull acc[BF][8];
#pragma unroll
        for (int o = 0; o < BF; o++)
#pragma unroll
            for (int q = 0; q < 8; q++)
                acc[o][q] = pack2(b0s[k8 * 16 + 2 * q], b0s[k8 * 16 + 2 * q + 1]);

        float uc[4][BF];
#pragma unroll
        for (int t = 0; t < 4; t++)
#pragma unroll
            for (int o = 0; o < BF; o++)
                uc[t][o] = __ldg(up[o] + (size_t)t * DTOT);

#pragma unroll 1
        for (int chunk = 0; chunk < 5; chunk++) {
            const int cb = chunk * 64;
            __syncthreads();                 // previous chunk consumers done
            // fill av tile [128 b][64 j] as float4
            for (int q = tid; q < 128 * 16; q += NTHR) {
                int r = q >> 4, c4 = (q & 15) * 4;
                int jg = cb + c4;
                const float* src = (jg < DZ)
                    ? (z + (size_t)(bbase + r) * DZ + jg)
                    : (x + (size_t)(bbase + r) * DX + (jg - DZ));
                *(float4*)(avs + r * AV_STRIDE + c4) = *(const float4*)src;
            }
            __syncthreads();                 // av tile ready

#pragma unroll 1
            for (int jj = 0; jj < 64; jj += 4) {
                float un[4][BF];
#pragma unroll
                for (int t = 0; t < 4; t++) {
                    int jn = cb + jj + 4 + t;
                    if (jn > 319) jn = 319;          // tail dummy (in-bounds)
#pragma unroll
                    for (int o = 0; o < BF; o++)
                        un[t][o] = __ldg(up[o] + (size_t)jn * DTOT);
                }
                float4 av4[BF];
#pragma unroll
                for (int o = 0; o < BF; o++)
                    av4[o] = *(const float4*)(avs + (blane + 64 * o) * AV_STRIDE + jj);

#pragma unroll
                for (int t = 0; t < 4; t++) {
                    const int jg = cb + jj + t;
                    const float2 ea = EAs[jg * 8 + k8];
                    const ulonglong2* wrp = (const ulonglong2*)(W0k + jg * 16);
                    ulonglong2 wA = wrp[0], wB = wrp[1], wC = wrp[2], wD = wrp[3];
#pragma unroll
                    for (int o = 0; o < BF; o++) {
                        float uu = uc[t][o];
                        float av = (t == 0) ? av4[o].x : (t == 1) ? av4[o].y
                                 : (t == 2) ? av4[o].z : av4[o].w;
                        float den = fmaf(uu, ea.y, ea.x);       // E + u*(1-E)
                        float s   = __fdividef(uu * av, den);
                        ull ss = pack2(s, s);
                        acc[o][0] = ffma2(ss, wA.x, acc[o][0]);
                        acc[o][1] = ffma2(ss, wA.y, acc[o][1]);
                        acc[o][2] = ffma2(ss, wB.x, acc[o][2]);
                        acc[o][3] = ffma2(ss, wB.y, acc[o][3]);
                        acc[o][4] = ffma2(ss, wC.x, acc[o][4]);
                        acc[o][5] = ffma2(ss, wC.y, acc[o][5]);
                        acc[o][6] = ffma2(ss, wD.x, acc[o][6]);
                        acc[o][7] = ffma2(ss, wD.y, acc[o][7]);
                    }
                }
#pragma unroll
                for (int t = 0; t < 4; t++)
#pragma unroll
                    for (int o = 0; o < BF; o++) uc[t][o] = un[t][o];
            }
        }

        // ---- epilogue per batch: diag correction, layers 1/2, logp ----
#pragma unroll 1
        for (int o = 0; o < BF; o++) {
            const int b = bbase + blane + 64 * o;
            float u_kk  = __ldg(u + (size_t)b * (DTOT * DTOT) + (size_t)kglob * DTOT + kglob);
            float av_kk = __ldg(x + (size_t)b * DX + (kglob - DZ));
            float2 eak  = EAs[kglob * 8 + k8];
            float skk   = __fdividef(u_kk * av_kk, fmaf(u_kk, eak.y, eak.x));
            const float* w0kk = W0k + kglob * 16;

            float hv[16];
#pragma unroll
            for (int q = 0; q < 8; q++) {
                float lo, hi;
                unpack2(acc[o][q], lo, hi);
                float c0 = fmaf(-skk, w0kk[2 * q],     lo);
                float c1 = fmaf(-skk, w0kk[2 * q + 1], hi);
                hv[2 * q]     = fmaxf(c0, NEG * c0);
                hv[2 * q + 1] = fmaxf(c1, NEG * c1);
            }
            float gv[16];
#pragma unroll
            for (int gg = 0; gg < 16; gg++) gv[gg] = b1s[k8 * 16 + gg];
#pragma unroll
            for (int hh = 0; hh < 16; hh++) {
                float hvv = hv[hh];
                const float4* w1r = (const float4*)(W1s + k8 * W1_STRIDE + hh * 16);
#pragma unroll
                for (int q = 0; q < 4; q++) {
                    float4 w = w1r[q];
                    gv[4 * q + 0] = fmaf(hvv, w.x, gv[4 * q + 0]);
                    gv[4 * q + 1] = fmaf(hvv, w.y, gv[4 * q + 1]);
                    gv[4 * q + 2] = fmaf(hvv, w.z, gv[4 * q + 2]);
                    gv[4 * q + 3] = fmaf(hvv, w.w, gv[4 * q + 3]);
                }
            }
            float mu = b2s[k8];
#pragma unroll
            for (int gg = 0; gg < 16; gg++) {
                float gl = fmaxf(gv[gg], NEG * gv[gg]);
                mu = fmaf(gl, W2s[k8 * 16 + gg], mu);
            }
            out[1 + (size_t)b * DTOT + kglob] = mu;

            float d = (av_kk - mu) * istd;
            lpsum += fmaf(-0.5f * d, d, lpc);
        }
    }

    // ---- deterministic CTA reduction ----
    red[tid] = lpsum;
    __syncthreads();
    for (int sft = 256; sft > 0; sft >>= 1) {
        if (tid < sft) red[tid] += red[tid + sft];
        __syncthreads();
    }
    if (tid == 0) g_partials[bsplit * 32 + kg] = red[0];
}

// ---------------------------------------------------------------------------
// latent kernel: k in [0,64) -> only j==k contributes
// ---------------------------------------------------------------------------
__global__ void __launch_bounds__(256)
latent_kernel(const float* __restrict__ z, const float* __restrict__ u,
              const float* __restrict__ mp,
              const float* __restrict__ W0, const float* __restrict__ b0,
              const float* __restrict__ W1, const float* __restrict__ b1,
              const float* __restrict__ W2, const float* __restrict__ b2,
              const float* __restrict__ logvar,
              float* __restrict__ out) {
    __shared__ float W1s[256], W0r[16], b0r[16], b1r[16], W2r[16];
    __shared__ float red[256];

    const int tid = threadIdx.x;
    const int k   = blockIdx.x;
    const int bq  = blockIdx.y;
    const int b   = bq * 256 + tid;

    if (tid < 16) {
        W0r[tid] = __ldg(W0 + ((size_t)k * DTOT + k) * 16 + tid);
        b0r[tid] = __ldg(b0 + k * 16 + tid);
        b1r[tid] = __ldg(b1 + k * 16 + tid);
        W2r[tid] = __ldg(W2 + k * 16 + tid);
    }
    W1s[tid] = __ldg(W1 + (size_t)k * 256 + tid);
    __syncthreads();

    float E  = __expf(-__ldg(mp + (size_t)k * DTOT + k));
    float uu = __ldg(u + (size_t)b * (DTOT * DTOT) + (size_t)k * DTOT + k);
    float zv = __ldg(z + (size_t)b * DZ + k);
    float adj = __fdividef(uu, fmaf(uu, 1.0f - E, E));
    float val = adj * zv;

    float hv[16];
#pragma unroll
    for (int i = 0; i < 16; i++) {
        float c = fmaf(val, W0r[i], b0r[i]);
        hv[i] = fmaxf(c, NEG * c);
    }
    float gv[16];
#pragma unroll
    for (int gg = 0; gg < 16; gg++) gv[gg] = b1r[gg];
#pragma unroll
    for (int hh = 0; hh < 16; hh++) {
        float hvv = hv[hh];
#pragma unroll
        for (int gg = 0; gg < 16; gg++)
            gv[gg] = fmaf(hvv, W1s[hh * 16 + gg], gv[gg]);
    }
    float mu = __ldg(b2 + k);
#pragma unroll
    for (int gg = 0; gg < 16; gg++) {
        float gl = fmaxf(gv[gg], NEG * gv[gg]);
        mu = fmaf(gl, W2r[gg], mu);
    }
    out[1 + (size_t)b * DTOT + k] = mu;

    float lv = __ldg(logvar + k);
    float istd = __expf(-0.5f * lv);
    float d = (zv - mu) * istd;
    red[tid] = fmaf(-0.5f * d, d, -0.5f * lv - HLOG2PI);
    __syncthreads();
    for (int sft = 128; sft > 0; sft >>= 1) {
        if (tid < sft) red[tid] += red[tid + sft];
        __syncthreads();
    }
    if (tid == 0) g_partials[128 + k * 4 + bq] = red[0];
}

// ---------------------------------------------------------------------------
// final: 384-thread deterministic reduction + std output
// ---------------------------------------------------------------------------
__global__ void final_kernel(const float* __restrict__ logvar,
                             float* __restrict__ out) {
    __shared__ float red[384];
    const int tid = threadIdx.x;
    red[tid] = g_partials[tid];
    __syncthreads();
    if (tid < 128) red[tid] += red[tid + 256];
    __syncthreads();
    for (int sft = 128; sft > 0; sft >>= 1) {
        if (tid < sft) red[tid] += red[tid + sft];
        __syncthreads();
    }
    if (tid == 0) out[0] = red[0] * (1.0f / 1024.0f);
    if (tid < DTOT) out[1 + BATCH * DTOT + tid] = expf(0.5f * __ldg(logvar + tid));
}

// ---------------------------------------------------------------------------
extern "C" void kernel_launch(void* const* d_in, const int* in_sizes, int n_in,
                              void* d_out, int out_size) {
    const float* x      = (const float*)d_in[0];
    const float* z      = (const float*)d_in[1];
    const float* u      = (const float*)d_in[2];
    const float* mp     = (const float*)d_in[3];
    const float* W0     = (const float*)d_in[4];
    const float* b0     = (const float*)d_in[5];
    const float* W1     = (const float*)d_in[6];
    const float* b1     = (const float*)d_in[7];
    const float* W2     = (const float*)d_in[8];
    const float* b2     = (const float*)d_in[9];
    const float* logvar = (const float*)d_in[10];
    float* out = (float*)d_out;

    cudaFuncSetAttribute(main_kernel, cudaFuncAttributeMaxDynamicSharedMemorySize,
                         SMEM_BYTES);

    main_kernel<<<dim3(32, 4), NTHR, SMEM_BYTES>>>(x, z, u, mp, W0, b0, W1, b1,
                                                   W2, b2, logvar, out);
    latent_kernel<<<dim3(64, 4), 256>>>(z, u, mp, W0, b0, W1, b1, W2, b2, logvar, out);
    final_kernel<<<1, 384>>>(logvar, out);
}